// round 5
// baseline (speedup 1.0000x reference)
#include <cuda_runtime.h>
#include <stdint.h>
#include <math.h>

#define NPV   32768          // nodes in perturbed graph
#define NNV   128            // nodes in non-perturbed graph
#define EPV   524288         // edges p
#define ENV   2048           // edges np
#define CH    128            // channels
#define WALKN 7
#define BATN  256
#define TOTP  (EPV + NPV)    // CSR entries p (edges + self loops)
#define TOTN  (ENV + NNV)
#define CC    (CH * CH)

// ---------------- device scratch (static, no allocation) ----------------
static __device__ int   g_deg_p[NPV];
static __device__ int   g_deg_n[NNV];
static __device__ float g_dinv_p[NPV];
static __device__ float g_dinv_n[NNV];
static __device__ int   g_rs_p[NPV + 1];
static __device__ int   g_rs_n[NNV + 1];
static __device__ int   g_cur_p[NPV];
static __device__ int   g_cur_n[NNV];
static __device__ int2  g_colw_p[TOTP];          // {src, float_bits(norm)}
static __device__ int2  g_colw_n[TOTN];
static __device__ float g_g[2][NPV * CH];        // ping-pong g = A^t x_p
static __device__ float g_gn[2][NNV * CH];
static __device__ float g_c[2][NPV];             // ping-pong c = A^t 1
static __device__ float g_cn[2][NNV];
static __device__ float g_P [(WALKN + 1) * CC];  // W^t   (P_0 = I)
static __device__ float g_PT[(WALKN + 1) * CC];  // (W^t)^T
static __device__ float g_Bv[(WALKN + 1) * CH];  // b^T W^t  (B_0 = b)
static __device__ float g_ptr[WALKN * BATN];     // block traces of g_t W^t
static __device__ float g_ntr[WALKN];
static __device__ float g_q [WALKN * BATN];      // q'_a = <c_a block, B_a>
static __device__ float g_qn[WALKN];
static __device__ int   g_is64_p;
static __device__ int   g_is64_n;

__device__ __forceinline__ int eget(const void* p, int is64, int i) {
    return is64 ? (int)((const long long*)p)[i] : ((const int*)p)[i];
}

// ---------------- init / zero ----------------
__global__ void k_init(const float* __restrict__ bg) {
    int i = blockIdx.x * blockDim.x + threadIdx.x;
    if (i < NPV)          { g_deg_p[i] = 0; g_c[0][i] = 1.0f; }
    if (i < NNV)          { g_deg_n[i] = 0; g_cn[0][i] = 1.0f; }
    if (i < WALKN * BATN) { g_ptr[i] = 0.0f; g_q[i] = 0.0f; }
    if (i < WALKN)        { g_ntr[i] = 0.0f; g_qn[i] = 0.0f; }
    if (i < CC)           { g_P[i] = ((i / CH) == (i % CH)) ? 1.0f : 0.0f; }
    if (i < CH)           { g_Bv[i] = bg[i]; }
    if (i == 0)           { g_is64_p = 1; g_is64_n = 1; }
}

// ---------------- dtype detection (int64 vs int32 edges) ----------------
// Safe region: first 2*E 32-bit words exist in BOTH layouts. If layout is
// int64, odd words are high halves of values < 32768 -> all zero.
__global__ void k_detect(const void* __restrict__ eip, const void* __restrict__ ein) {
    int i = blockIdx.x * blockDim.x + threadIdx.x;
    if (i < EPV) {
        if (((const int*)eip)[2 * i + 1] != 0) g_is64_p = 0;
    } else {
        int j = i - EPV;  // j < ENV
        if (((const int*)ein)[2 * j + 1] != 0) g_is64_n = 0;
    }
}

// ---------------- degree count at dst ----------------
__global__ void k_deg(const void* __restrict__ eip, const void* __restrict__ ein) {
    int i = blockIdx.x * blockDim.x + threadIdx.x;
    if (i < EPV) {
        int d = eget(eip, g_is64_p, EPV + i);
        atomicAdd(&g_deg_p[d], 1);
    } else {
        int j = i - EPV;
        int d = eget(ein, g_is64_n, ENV + j);
        atomicAdd(&g_deg_n[d], 1);
    }
}

// ---------------- scan: dinv + CSR row offsets ----------------
__global__ void k_scan() {
    __shared__ int sh[1024];
    int tid = threadIdx.x;
    int base = tid * 32;
    int lsum = 0;
    for (int j = 0; j < 32; j++) {
        int L = g_deg_p[base + j] + 1;   // + self loop
        lsum += L;
        g_dinv_p[base + j] = rsqrtf((float)L);
    }
    sh[tid] = lsum;
    __syncthreads();
    for (int ofs = 1; ofs < 1024; ofs <<= 1) {
        int v = (tid >= ofs) ? sh[tid - ofs] : 0;
        __syncthreads();
        sh[tid] += v;
        __syncthreads();
    }
    int off = sh[tid] - lsum;  // exclusive
    for (int j = 0; j < 32; j++) {
        g_rs_p[base + j] = off;
        off += g_deg_p[base + j] + 1;
    }
    if (tid == 1023) g_rs_p[NPV] = off;
    __syncthreads();
    if (tid < NNV) g_dinv_n[tid] = rsqrtf((float)(g_deg_n[tid] + 1));
    if (tid == 0) {
        int o = 0;
        for (int i = 0; i < NNV; i++) { g_rs_n[i] = o; o += g_deg_n[i] + 1; }
        g_rs_n[NNV] = o;
    }
}

__global__ void k_cur() {
    int i = blockIdx.x * blockDim.x + threadIdx.x;
    if (i < NPV) g_cur_p[i] = g_rs_p[i];
    if (i < NNV) g_cur_n[i] = g_rs_n[i];
}

// ---------------- CSR fill (edges + self loops, with norms) ----------------
__global__ void k_fill(const void* __restrict__ eip, const void* __restrict__ ein) {
    int i = blockIdx.x * blockDim.x + threadIdx.x;
    if (i < EPV) {
        int s = eget(eip, g_is64_p, i);
        int d = eget(eip, g_is64_p, EPV + i);
        float w = g_dinv_p[s] * g_dinv_p[d];
        int pos = atomicAdd(&g_cur_p[d], 1);
        g_colw_p[pos] = make_int2(s, __float_as_int(w));
    } else if (i < EPV + NPV) {
        int n = i - EPV;
        float di = g_dinv_p[n];
        int pos = atomicAdd(&g_cur_p[n], 1);
        g_colw_p[pos] = make_int2(n, __float_as_int(di * di));
    } else if (i < EPV + NPV + ENV) {
        int j = i - EPV - NPV;
        int s = eget(ein, g_is64_n, j);
        int d = eget(ein, g_is64_n, ENV + j);
        float w = g_dinv_n[s] * g_dinv_n[d];
        int pos = atomicAdd(&g_cur_n[d], 1);
        g_colw_n[pos] = make_int2(s, __float_as_int(w));
    } else if (i < EPV + NPV + ENV + NNV) {
        int n = i - EPV - NPV - ENV;
        float di = g_dinv_n[n];
        int pos = atomicAdd(&g_cur_n[n], 1);
        g_colw_n[pos] = make_int2(n, __float_as_int(di * di));
    }
}

// ---------------- W powers: P_t = P_{t-1} @ W, B_t = B_{t-1} @ W ----------------
__global__ void k_wpow(const float* __restrict__ W, int t) {
    __shared__ float prev[CH];
    int c = threadIdx.x;
    int r = blockIdx.x;
    const float* prow = (r < CH) ? (g_P + (t - 1) * CC + r * CH)
                                 : (g_Bv + (t - 1) * CH);
    prev[c] = prow[c];
    __syncthreads();
    float acc = 0.0f;
#pragma unroll 8
    for (int m = 0; m < CH; m++) acc = fmaf(prev[m], W[m * CH + c], acc);
    if (r < CH) {
        g_P[t * CC + r * CH + c] = acc;
        g_PT[t * CC + c * CH + r] = acc;   // transposed copy for fused trace
    } else {
        g_Bv[t * CH + c] = acc;
    }
}

// ---------------- main per-step kernel: g <- A g, c <- A c, fused traces ----------------
__global__ void __launch_bounds__(256) k_agg(const float* __restrict__ xp,
                                             const float* __restrict__ xnp, int a) {
    int gw   = blockIdx.x * 8 + (threadIdx.x >> 5);   // warp per dst row
    int lane = threadIdx.x & 31;
    int pa = (a - 1) & 1, ca = a & 1;

    if (gw < NPV) {
        const float4* g4  = (const float4*)((a == 1) ? xp : g_g[pa]);
        const float*  cin = g_c[pa];
        int s0 = g_rs_p[gw], s1 = g_rs_p[gw + 1];
        float ax = 0.f, ay = 0.f, az = 0.f, aw = 0.f, cacc = 0.f;
        int e = s0;
        for (; e + 2 <= s1; e += 2) {                 // 2-deep pipeline (MLP)
            int2 cw0 = g_colw_p[e];
            int2 cw1 = g_colw_p[e + 1];
            float4 v0 = g4[cw0.x * 32 + lane];
            float4 v1 = g4[cw1.x * 32 + lane];
            float w0 = __int_as_float(cw0.y), w1 = __int_as_float(cw1.y);
            ax = fmaf(w0, v0.x, ax); ay = fmaf(w0, v0.y, ay);
            az = fmaf(w0, v0.z, az); aw = fmaf(w0, v0.w, aw);
            ax = fmaf(w1, v1.x, ax); ay = fmaf(w1, v1.y, ay);
            az = fmaf(w1, v1.z, az); aw = fmaf(w1, v1.w, aw);
            if (lane == 0) cacc += w0 * cin[cw0.x] + w1 * cin[cw1.x];
        }
        if (e < s1) {
            int2 cw0 = g_colw_p[e];
            float4 v0 = g4[cw0.x * 32 + lane];
            float w0 = __int_as_float(cw0.y);
            ax = fmaf(w0, v0.x, ax); ay = fmaf(w0, v0.y, ay);
            az = fmaf(w0, v0.z, az); aw = fmaf(w0, v0.w, aw);
            if (lane == 0) cacc += w0 * cin[cw0.x];
        }
        ((float4*)g_g[ca])[gw * 32 + lane] = make_float4(ax, ay, az, aw);

        // fused block trace: row r=gw contributes  g[r,:] . W^a[:, r&127]
        int k = gw & 127, bb = gw >> 7;
        float4 wt = ((const float4*)(g_PT + a * CC + k * CH))[lane];
        float part = ax * wt.x + ay * wt.y + az * wt.z + aw * wt.w;
        part += __shfl_xor_sync(0xffffffffu, part, 16);
        part += __shfl_xor_sync(0xffffffffu, part, 8);
        part += __shfl_xor_sync(0xffffffffu, part, 4);
        part += __shfl_xor_sync(0xffffffffu, part, 2);
        part += __shfl_xor_sync(0xffffffffu, part, 1);
        if (lane == 0) {
            atomicAdd(&g_ptr[(a - 1) * BATN + bb], part);
            g_c[ca][gw] = cacc;
            atomicAdd(&g_q[(a - 1) * BATN + bb], cacc * g_Bv[a * CH + k]);
        }
    } else {
        int w2 = gw - NPV;                            // np graph, 128 dst rows
        const float4* g4  = (const float4*)((a == 1) ? xnp : g_gn[pa]);
        const float*  cin = g_cn[pa];
        int s0 = g_rs_n[w2], s1 = g_rs_n[w2 + 1];
        float ax = 0.f, ay = 0.f, az = 0.f, aw = 0.f, cacc = 0.f;
        for (int e = s0; e < s1; e++) {
            int2 cw0 = g_colw_n[e];
            float4 v0 = g4[cw0.x * 32 + lane];
            float w0 = __int_as_float(cw0.y);
            ax = fmaf(w0, v0.x, ax); ay = fmaf(w0, v0.y, ay);
            az = fmaf(w0, v0.z, az); aw = fmaf(w0, v0.w, aw);
            if (lane == 0) cacc += w0 * cin[cw0.x];
        }
        ((float4*)g_gn[ca])[w2 * 32 + lane] = make_float4(ax, ay, az, aw);
        float4 wt = ((const float4*)(g_PT + a * CC + w2 * CH))[lane];
        float part = ax * wt.x + ay * wt.y + az * wt.z + aw * wt.w;
        part += __shfl_xor_sync(0xffffffffu, part, 16);
        part += __shfl_xor_sync(0xffffffffu, part, 8);
        part += __shfl_xor_sync(0xffffffffu, part, 4);
        part += __shfl_xor_sync(0xffffffffu, part, 2);
        part += __shfl_xor_sync(0xffffffffu, part, 1);
        if (lane == 0) {
            atomicAdd(&g_ntr[a - 1], part);
            g_cn[ca][w2] = cacc;
            atomicAdd(&g_qn[a - 1], cacc * g_Bv[a * CH + w2]);
        }
    }
}

// ---------------- epilogue: bias corr, standardize, MLP, sigmoid ----------------
__global__ void k_epi(const float* __restrict__ y,  const float* __restrict__ bg,
                      const float* __restrict__ W1, const float* __restrict__ b1,
                      const float* __restrict__ W2, const float* __restrict__ b2,
                      float* __restrict__ out) {
    __shared__ float sh[BATN];
    int b = threadIdx.x;
    float sumb = 0.f;
    for (int k = 0; k < CH; k++) sumb += bg[k];
    float ysc = (y[b] - 0.5f) * 2.0f;

    float v[WALKN];
    float cp = 0.f, cn = 0.f;
    for (int s = 0; s < WALKN; s++) {
        float qp = (s == 0) ? sumb : g_q[(s - 1) * BATN + b];
        float qn = (s == 0) ? sumb : g_qn[s - 1];
        cp += qp; cn += qn;
        float pv = g_ptr[s * BATN + b] + cp;
        float nv = g_ntr[s] + cn;
        v[s] = (pv - nv) * ysc;
    }
    // standardize each column over batch (ddof=1)
    for (int s = 0; s < WALKN; s++) {
        __syncthreads();
        sh[b] = v[s];
        __syncthreads();
        for (int ofs = 128; ofs > 0; ofs >>= 1) {
            if (b < ofs) sh[b] += sh[b + ofs];
            __syncthreads();
        }
        float mu = sh[0] * (1.0f / BATN);
        __syncthreads();
        float d = v[s] - mu;
        sh[b] = d * d;
        __syncthreads();
        for (int ofs = 128; ofs > 0; ofs >>= 1) {
            if (b < ofs) sh[b] += sh[b + ofs];
            __syncthreads();
        }
        float sd = sqrtf(sh[0] * (1.0f / (BATN - 1)));
        v[s] = d / sd;
    }
    // MLP 7 -> 15 -> 1, sigmoid
    float o2 = b2[0];
    for (int j = 0; j < 15; j++) {
        float h = b1[j];
        for (int s = 0; s < WALKN; s++) h = fmaf(v[s], W1[s * 15 + j], h);
        h = fmaxf(h, 0.0f);
        o2 = fmaf(h, W2[j], o2);
    }
    out[b] = 1.0f / (1.0f + expf(-o2));
}

// ---------------- launch ----------------
extern "C" void kernel_launch(void* const* d_in, const int* in_sizes, int n_in,
                              void* d_out, int out_size) {
    const float* x_p  = (const float*)d_in[0];
    const float* x_np = (const float*)d_in[1];
    const float* y    = (const float*)d_in[2];
    const void*  eip  = d_in[3];
    const void*  ein  = d_in[4];
    const float* W    = (const float*)d_in[5];
    const float* bg   = (const float*)d_in[6];
    const float* W1   = (const float*)d_in[7];
    const float* b1   = (const float*)d_in[8];
    const float* W2   = (const float*)d_in[9];
    const float* b2   = (const float*)d_in[10];
    float* out = (float*)d_out;

    k_init<<<128, 256>>>(bg);
    k_detect<<<(EPV + ENV) / 256, 256>>>(eip, ein);
    k_deg<<<(EPV + ENV) / 256, 256>>>(eip, ein);
    k_scan<<<1, 1024>>>();
    k_cur<<<128, 256>>>();
    k_fill<<<(EPV + NPV + ENV + NNV + 255) / 256, 256>>>(eip, ein);
    for (int t = 1; t <= WALKN; t++) k_wpow<<<CH + 1, CH>>>(W, t);
    for (int a = 1; a <= WALKN; a++) k_agg<<<(NPV + NNV) / 8, 256>>>(x_p, x_np, a);
    k_epi<<<1, BATN>>>(y, bg, W1, b1, W2, b2, out);
    (void)in_sizes; (void)n_in; (void)out_size;
}

// round 6
// speedup vs baseline: 1.4538x; 1.4538x over previous
#include <cuda_runtime.h>
#include <stdint.h>
#include <math.h>

#define NPV   32768          // nodes in perturbed graph
#define NNV   128            // nodes in non-perturbed graph
#define EPV   524288         // edges p
#define ENV   2048           // edges np
#define CH    128            // channels
#define WALKN 7
#define BATN  256
#define TOTP  (EPV + NPV)    // CSR entries p (edges + self loops)
#define TOTN  (ENV + NNV)
#define CC    (CH * CH)

// ---------------- device scratch (static, no allocation) ----------------
static __device__ int   g_deg_p[NPV];
static __device__ int   g_deg_n[NNV];
static __device__ float g_dinv_p[NPV];
static __device__ float g_dinv_n[NNV];
static __device__ int   g_rs_p[NPV + 1];
static __device__ int   g_rs_n[NNV + 1];
static __device__ int   g_cur_p[NPV];
static __device__ int   g_cur_n[NNV];
static __device__ int   g_bsum[32];
static __device__ int   g_boff[32];
static __device__ int2  g_colw_p[TOTP];          // {src, float_bits(norm)}
static __device__ int2  g_colw_n[TOTN];
static __device__ float g_g[2][NPV * CH];        // ping-pong g = A^t x_p
static __device__ float g_gn[2][NNV * CH];
static __device__ float g_c[2][NPV];             // ping-pong c = A^t 1
static __device__ float g_cn[2][NNV];
static __device__ float g_PT[(WALKN + 1) * CC];  // (W^t)^T
static __device__ float g_Bv[(WALKN + 1) * CH];  // b^T W^t
static __device__ float g_ptr[WALKN * BATN];     // block traces of g_t W^t
static __device__ float g_ntr[WALKN];
static __device__ float g_q [WALKN * BATN];      // q'_a = <c_a block, B_a>
static __device__ float g_qn[WALKN];
static __device__ int   g_is64_p;
static __device__ int   g_is64_n;

__device__ __forceinline__ int eget(const void* p, int is64, int i) {
    return is64 ? (int)((const long long*)p)[i] : ((const int*)p)[i];
}

// ---------------- init / zero ----------------
__global__ void k_init() {
    int i = blockIdx.x * blockDim.x + threadIdx.x;
    if (i < NPV)          { g_deg_p[i] = 0; g_c[0][i] = 1.0f; }
    if (i < NNV)          { g_deg_n[i] = 0; g_cn[0][i] = 1.0f; }
    if (i < WALKN * BATN) { g_ptr[i] = 0.0f; g_q[i] = 0.0f; }
    if (i < WALKN)        { g_ntr[i] = 0.0f; g_qn[i] = 0.0f; }
    if (i == 0)           { g_is64_p = 1; g_is64_n = 1; }
}

// ---------------- dtype detection (int64 vs int32 edges) ----------------
// Safe region: first 2*E 32-bit words exist in BOTH layouts. If layout is
// int64, odd words are high halves of values < 32768 -> all zero.
__global__ void k_detect(const void* __restrict__ eip, const void* __restrict__ ein) {
    int i = blockIdx.x * blockDim.x + threadIdx.x;
    if (i < EPV) {
        if (((const int*)eip)[2 * i + 1] != 0) g_is64_p = 0;
    } else {
        int j = i - EPV;  // j < ENV
        if (((const int*)ein)[2 * j + 1] != 0) g_is64_n = 0;
    }
}

// ---------------- degree count at dst ----------------
__global__ void k_deg(const void* __restrict__ eip, const void* __restrict__ ein) {
    int i = blockIdx.x * blockDim.x + threadIdx.x;
    if (i < EPV) {
        int d = eget(eip, g_is64_p, EPV + i);
        atomicAdd(&g_deg_p[d], 1);
    } else {
        int j = i - EPV;
        int d = eget(ein, g_is64_n, ENV + j);
        atomicAdd(&g_deg_n[d], 1);
    }
}

// ---------------- parallel scan: pass 1 (per-block local scan, 32 blocks) ----
__global__ void k_scan1() {
    __shared__ int sh[1024];
    int t = threadIdx.x;
    int i = blockIdx.x * 1024 + t;
    int L = g_deg_p[i] + 1;                // + self loop
    g_dinv_p[i] = rsqrtf((float)L);
    sh[t] = L;
    __syncthreads();
    for (int o = 1; o < 1024; o <<= 1) {
        int v = (t >= o) ? sh[t - o] : 0;
        __syncthreads();
        sh[t] += v;
        __syncthreads();
    }
    g_rs_p[i] = sh[t] - L;                 // local exclusive
    if (t == 1023) g_bsum[blockIdx.x] = sh[1023];
}

// ---------------- pass 2: scan 32 block sums + full np-graph scan ----------
__global__ void k_scan2() {
    __shared__ int shn[NNV];
    int t = threadIdx.x;                   // 128 threads
    if (t < 32) {
        int v = g_bsum[t];
        int s = v;
        for (int o = 1; o < 32; o <<= 1) {
            int u = __shfl_up_sync(0xffffffffu, s, o);
            if (t >= o) s += u;
        }
        g_boff[t] = s - v;
    }
    int L = g_deg_n[t] + 1;
    g_dinv_n[t] = rsqrtf((float)L);
    shn[t] = L;
    __syncthreads();
    for (int o = 1; o < 128; o <<= 1) {
        int v = (t >= o) ? shn[t - o] : 0;
        __syncthreads();
        shn[t] += v;
        __syncthreads();
    }
    int ex = shn[t] - L;
    g_rs_n[t] = ex;
    g_cur_n[t] = ex;
    if (t == 0) g_rs_n[NNV] = TOTN;
}

// ---------------- pass 3: add block offsets, init cursors -------------------
__global__ void k_scan3() {
    int i = blockIdx.x * blockDim.x + threadIdx.x;   // NPV threads
    int v = g_rs_p[i] + g_boff[i >> 10];
    g_rs_p[i] = v;
    g_cur_p[i] = v;
    if (i == 0) g_rs_p[NPV] = TOTP;
}

// ---------------- CSR fill (edges + self loops, with norms) ----------------
__global__ void k_fill(const void* __restrict__ eip, const void* __restrict__ ein) {
    int i = blockIdx.x * blockDim.x + threadIdx.x;
    if (i < EPV) {
        int s = eget(eip, g_is64_p, i);
        int d = eget(eip, g_is64_p, EPV + i);
        float w = g_dinv_p[s] * g_dinv_p[d];
        int pos = atomicAdd(&g_cur_p[d], 1);
        g_colw_p[pos] = make_int2(s, __float_as_int(w));
    } else if (i < EPV + NPV) {
        int n = i - EPV;
        float di = g_dinv_p[n];
        int pos = atomicAdd(&g_cur_p[n], 1);
        g_colw_p[pos] = make_int2(n, __float_as_int(di * di));
    } else if (i < EPV + NPV + ENV) {
        int j = i - EPV - NPV;
        int s = eget(ein, g_is64_n, j);
        int d = eget(ein, g_is64_n, ENV + j);
        float w = g_dinv_n[s] * g_dinv_n[d];
        int pos = atomicAdd(&g_cur_n[d], 1);
        g_colw_n[pos] = make_int2(s, __float_as_int(w));
    } else if (i < EPV + NPV + ENV + NNV) {
        int n = i - EPV - NPV - ENV;
        float di = g_dinv_n[n];
        int pos = atomicAdd(&g_cur_n[n], 1);
        g_colw_n[pos] = make_int2(n, __float_as_int(di * di));
    }
}

// ---------------- all W powers in ONE kernel: row-resident recurrence -------
// P_t[r,:] = P_{t-1}[r,:] @ W  is independent per row r. Block r keeps its row
// in shared memory and iterates all WALKN powers; W stays L1-resident after
// the first sweep. Block CH handles the bias row b^T W^t.
__global__ void k_wpow_all(const float* __restrict__ W, const float* __restrict__ bg) {
    __shared__ float prev[CH];
    int c = threadIdx.x;
    int r = blockIdx.x;
    prev[c] = (r < CH) ? ((c == r) ? 1.0f : 0.0f) : bg[c];
    __syncthreads();
    for (int t = 1; t <= WALKN; t++) {
        float acc = 0.0f;
#pragma unroll 16
        for (int m = 0; m < CH; m++) acc = fmaf(prev[m], W[m * CH + c], acc);
        __syncthreads();
        prev[c] = acc;
        if (r < CH) g_PT[t * CC + c * CH + r] = acc;   // transposed for fused trace
        else        g_Bv[t * CH + c] = acc;
        __syncthreads();
    }
}

// ---------------- main per-step kernel: g <- A g, c <- A c, fused traces ----
__global__ void __launch_bounds__(256) k_agg(const float* __restrict__ xp,
                                             const float* __restrict__ xnp,
                                             int a, int last) {
    int gw   = blockIdx.x * 8 + (threadIdx.x >> 5);   // warp per dst row
    int lane = threadIdx.x & 31;
    int pa = (a - 1) & 1, ca = a & 1;

    if (gw < NPV) {
        const float4* g4  = (const float4*)((a == 1) ? xp : g_g[pa]);
        const float*  cin = g_c[pa];
        int s0 = g_rs_p[gw], s1 = g_rs_p[gw + 1];
        float ax = 0.f, ay = 0.f, az = 0.f, aw = 0.f, cacc = 0.f;
        int e = s0;
        for (; e + 2 <= s1; e += 2) {                 // 2-deep pipeline (MLP)
            int2 cw0 = g_colw_p[e];
            int2 cw1 = g_colw_p[e + 1];
            float4 v0 = g4[cw0.x * 32 + lane];
            float4 v1 = g4[cw1.x * 32 + lane];
            float w0 = __int_as_float(cw0.y), w1 = __int_as_float(cw1.y);
            ax = fmaf(w0, v0.x, ax); ay = fmaf(w0, v0.y, ay);
            az = fmaf(w0, v0.z, az); aw = fmaf(w0, v0.w, aw);
            ax = fmaf(w1, v1.x, ax); ay = fmaf(w1, v1.y, ay);
            az = fmaf(w1, v1.z, az); aw = fmaf(w1, v1.w, aw);
            if (!last && lane == 0) cacc += w0 * cin[cw0.x] + w1 * cin[cw1.x];
        }
        if (e < s1) {
            int2 cw0 = g_colw_p[e];
            float4 v0 = g4[cw0.x * 32 + lane];
            float w0 = __int_as_float(cw0.y);
            ax = fmaf(w0, v0.x, ax); ay = fmaf(w0, v0.y, ay);
            az = fmaf(w0, v0.z, az); aw = fmaf(w0, v0.w, aw);
            if (!last && lane == 0) cacc += w0 * cin[cw0.x];
        }
        if (!last)   // g_WALKN and c_WALKN are never consumed downstream
            ((float4*)g_g[ca])[gw * 32 + lane] = make_float4(ax, ay, az, aw);

        // fused block trace: row r=gw contributes  g[r,:] . W^a[:, r&127]
        int k = gw & 127, bb = gw >> 7;
        float4 wt = ((const float4*)(g_PT + a * CC + k * CH))[lane];
        float part = ax * wt.x + ay * wt.y + az * wt.z + aw * wt.w;
        part += __shfl_xor_sync(0xffffffffu, part, 16);
        part += __shfl_xor_sync(0xffffffffu, part, 8);
        part += __shfl_xor_sync(0xffffffffu, part, 4);
        part += __shfl_xor_sync(0xffffffffu, part, 2);
        part += __shfl_xor_sync(0xffffffffu, part, 1);
        if (lane == 0) {
            atomicAdd(&g_ptr[(a - 1) * BATN + bb], part);
            if (!last) {
                g_c[ca][gw] = cacc;
                atomicAdd(&g_q[(a - 1) * BATN + bb], cacc * g_Bv[a * CH + k]);
            }
        }
    } else {
        int w2 = gw - NPV;                            // np graph, 128 dst rows
        const float4* g4  = (const float4*)((a == 1) ? xnp : g_gn[pa]);
        const float*  cin = g_cn[pa];
        int s0 = g_rs_n[w2], s1 = g_rs_n[w2 + 1];
        float ax = 0.f, ay = 0.f, az = 0.f, aw = 0.f, cacc = 0.f;
        for (int e = s0; e < s1; e++) {
            int2 cw0 = g_colw_n[e];
            float4 v0 = g4[cw0.x * 32 + lane];
            float w0 = __int_as_float(cw0.y);
            ax = fmaf(w0, v0.x, ax); ay = fmaf(w0, v0.y, ay);
            az = fmaf(w0, v0.z, az); aw = fmaf(w0, v0.w, aw);
            if (!last && lane == 0) cacc += w0 * cin[cw0.x];
        }
        if (!last)
            ((float4*)g_gn[ca])[w2 * 32 + lane] = make_float4(ax, ay, az, aw);
        float4 wt = ((const float4*)(g_PT + a * CC + w2 * CH))[lane];
        float part = ax * wt.x + ay * wt.y + az * wt.z + aw * wt.w;
        part += __shfl_xor_sync(0xffffffffu, part, 16);
        part += __shfl_xor_sync(0xffffffffu, part, 8);
        part += __shfl_xor_sync(0xffffffffu, part, 4);
        part += __shfl_xor_sync(0xffffffffu, part, 2);
        part += __shfl_xor_sync(0xffffffffu, part, 1);
        if (lane == 0) {
            atomicAdd(&g_ntr[a - 1], part);
            if (!last) {
                g_cn[ca][w2] = cacc;
                atomicAdd(&g_qn[a - 1], cacc * g_Bv[a * CH + w2]);
            }
        }
    }
}

// ---------------- epilogue: bias corr, standardize, MLP, sigmoid ----------------
__global__ void k_epi(const float* __restrict__ y,  const float* __restrict__ bg,
                      const float* __restrict__ W1, const float* __restrict__ b1,
                      const float* __restrict__ W2, const float* __restrict__ b2,
                      float* __restrict__ out) {
    __shared__ float sh[BATN];
    int b = threadIdx.x;
    float sumb = 0.f;
    for (int k = 0; k < CH; k++) sumb += bg[k];
    float ysc = (y[b] - 0.5f) * 2.0f;

    float v[WALKN];
    float cp = 0.f, cn = 0.f;
    for (int s = 0; s < WALKN; s++) {
        float qp = (s == 0) ? sumb : g_q[(s - 1) * BATN + b];
        float qn = (s == 0) ? sumb : g_qn[s - 1];
        cp += qp; cn += qn;
        float pv = g_ptr[s * BATN + b] + cp;
        float nv = g_ntr[s] + cn;
        v[s] = (pv - nv) * ysc;
    }
    for (int s = 0; s < WALKN; s++) {
        __syncthreads();
        sh[b] = v[s];
        __syncthreads();
        for (int ofs = 128; ofs > 0; ofs >>= 1) {
            if (b < ofs) sh[b] += sh[b + ofs];
            __syncthreads();
        }
        float mu = sh[0] * (1.0f / BATN);
        __syncthreads();
        float d = v[s] - mu;
        sh[b] = d * d;
        __syncthreads();
        for (int ofs = 128; ofs > 0; ofs >>= 1) {
            if (b < ofs) sh[b] += sh[b + ofs];
            __syncthreads();
        }
        float sd = sqrtf(sh[0] * (1.0f / (BATN - 1)));
        v[s] = d / sd;
    }
    float o2 = b2[0];
    for (int j = 0; j < 15; j++) {
        float h = b1[j];
        for (int s = 0; s < WALKN; s++) h = fmaf(v[s], W1[s * 15 + j], h);
        h = fmaxf(h, 0.0f);
        o2 = fmaf(h, W2[j], o2);
    }
    out[b] = 1.0f / (1.0f + expf(-o2));
}

// ---------------- launch ----------------
extern "C" void kernel_launch(void* const* d_in, const int* in_sizes, int n_in,
                              void* d_out, int out_size) {
    const float* x_p  = (const float*)d_in[0];
    const float* x_np = (const float*)d_in[1];
    const float* y    = (const float*)d_in[2];
    const void*  eip  = d_in[3];
    const void*  ein  = d_in[4];
    const float* W    = (const float*)d_in[5];
    const float* bg   = (const float*)d_in[6];
    const float* W1   = (const float*)d_in[7];
    const float* b1   = (const float*)d_in[8];
    const float* W2   = (const float*)d_in[9];
    const float* b2   = (const float*)d_in[10];
    float* out = (float*)d_out;

    k_init<<<128, 256>>>();
    k_detect<<<(EPV + ENV) / 256, 256>>>(eip, ein);
    k_deg<<<(EPV + ENV) / 256, 256>>>(eip, ein);
    k_scan1<<<32, 1024>>>();
    k_scan2<<<1, 128>>>();
    k_scan3<<<NPV / 256, 256>>>();
    k_fill<<<(EPV + NPV + ENV + NNV + 255) / 256, 256>>>(eip, ein);
    k_wpow_all<<<CH + 1, CH>>>(W, bg);
    for (int a = 1; a <= WALKN; a++)
        k_agg<<<(NPV + NNV) / 8, 256>>>(x_p, x_np, a, a == WALKN);
    k_epi<<<1, BATN>>>(y, bg, W1, b1, W2, b2, out);
    (void)in_sizes; (void)n_in; (void)out_size;
}

// round 7
// speedup vs baseline: 1.5448x; 1.0626x over previous
#include <cuda_runtime.h>
#include <stdint.h>
#include <math.h>

#define NPV   32768          // nodes in perturbed graph
#define NNV   128            // nodes in non-perturbed graph
#define EPV   524288         // edges p
#define ENV   2048           // edges np
#define CH    128            // channels
#define WALKN 7
#define BATN  256
#define TOTP  (EPV + NPV)    // CSR entries p (edges + self loops)
#define TOTN  (ENV + NNV)
#define CC    (CH * CH)

// ---------------- device scratch (static, no allocation) ----------------
static __device__ int   g_deg_p[NPV];
static __device__ int   g_deg_n[NNV];
static __device__ float g_dinv_p[NPV];
static __device__ float g_dinv_n[NNV];
static __device__ int   g_rs_p[NPV + 1];
static __device__ int   g_rs_n[NNV + 1];
static __device__ int   g_cur_p[NPV];
static __device__ int   g_cur_n[NNV];
static __device__ int   g_bsum[32];
static __device__ int   g_boff[32];
static __device__ int2  g_colw_p[TOTP];          // {src, float_bits(norm)}
static __device__ int2  g_colw_n[TOTN];
static __device__ float g_g[2][NPV * CH];        // ping-pong g = A^t x_p
static __device__ float g_gn[2][NNV * CH];
static __device__ float g_c[2][NPV];             // ping-pong c = A^t 1
static __device__ float g_cn[2][NNV];
static __device__ float g_PT[(WALKN + 1) * CC];  // (W^t)^T
static __device__ float g_Bv[(WALKN + 1) * CH];  // b^T W^t
static __device__ float g_ptr[WALKN * BATN];     // block traces of g_t W^t
static __device__ float g_ntr[WALKN];
static __device__ float g_q [WALKN * BATN];      // q'_a = <c_a block, B_a>
static __device__ float g_qn[WALKN];
// zero-initialized at load; k_epi resets to 0 at the end of EVERY run, so each
// execution of the launch sequence starts from the identical state.
static __device__ int   g_not64_p;
static __device__ int   g_not64_n;
static __device__ int   g_bnz;                   // any(b != 0)?

__device__ __forceinline__ int eget(const void* p, int is64, int i) {
    return is64 ? (int)((const long long*)p)[i] : ((const int*)p)[i];
}

// ---------------- fused init + dtype detection ----------------
// int64 vs int32 edges: first 2*E 32-bit words exist in BOTH layouts. If the
// layout is int64, odd words are high halves of values < 32768 -> all zero.
// EPV and ENV are multiples of 256, so no warp straddles the two regions.
__global__ void k_prep(const void* __restrict__ eip, const void* __restrict__ ein) {
    int i = blockIdx.x * blockDim.x + threadIdx.x;
    bool nz = false;
    int which = 0;
    if (i < EPV) {
        nz = ((const int*)eip)[2 * i + 1] != 0;
        which = 1;
    } else {
        int j = i - EPV;  // j < ENV
        nz = ((const int*)ein)[2 * j + 1] != 0;
        which = 2;
    }
    unsigned m = __ballot_sync(0xffffffffu, nz);
    if (m && (threadIdx.x & 31) == 0)
        atomicOr(which == 1 ? &g_not64_p : &g_not64_n, 1);

    if (i < NPV)          { g_deg_p[i] = 0; g_c[0][i] = 1.0f; }
    if (i < NNV)          { g_deg_n[i] = 0; g_cn[0][i] = 1.0f; }
    if (i < WALKN * BATN) { g_ptr[i] = 0.0f; g_q[i] = 0.0f; }
    if (i < WALKN)        { g_ntr[i] = 0.0f; g_qn[i] = 0.0f; }
}

// ---------------- degree count at dst ----------------
__global__ void k_deg(const void* __restrict__ eip, const void* __restrict__ ein) {
    int i = blockIdx.x * blockDim.x + threadIdx.x;
    if (i < EPV) {
        int d = eget(eip, !g_not64_p, EPV + i);
        atomicAdd(&g_deg_p[d], 1);
    } else {
        int j = i - EPV;
        int d = eget(ein, !g_not64_n, ENV + j);
        atomicAdd(&g_deg_n[d], 1);
    }
}

// ---------------- parallel scan pass 1: warp-shuffle local scan, 32 blocks --
__global__ void k_scan1() {
    __shared__ int ws[32];
    int t = threadIdx.x, lane = t & 31, w = t >> 5;
    int i = blockIdx.x * 1024 + t;
    int L = g_deg_p[i] + 1;                // + self loop
    g_dinv_p[i] = rsqrtf((float)L);
    int s = L;
    for (int o = 1; o < 32; o <<= 1) {
        int u = __shfl_up_sync(0xffffffffu, s, o);
        if (lane >= o) s += u;
    }
    if (lane == 31) ws[w] = s;
    __syncthreads();
    if (w == 0) {
        int v = ws[lane], ss = v;
        for (int o = 1; o < 32; o <<= 1) {
            int u = __shfl_up_sync(0xffffffffu, ss, o);
            if (lane >= o) ss += u;
        }
        ws[lane] = ss - v;                 // exclusive warp offsets
    }
    __syncthreads();
    int ex = s - L + ws[w];
    g_rs_p[i] = ex;
    if (t == 1023) g_bsum[blockIdx.x] = ex + L;
}

// ---------------- pass 2: scan 32 block sums + full np-graph scan ----------
__global__ void k_scan2() {
    __shared__ int ws[4];
    int t = threadIdx.x, lane = t & 31, w = t >> 5;   // 128 threads
    if (t < 32) {
        int v = g_bsum[t], s = v;
        for (int o = 1; o < 32; o <<= 1) {
            int u = __shfl_up_sync(0xffffffffu, s, o);
            if (t >= o) s += u;
        }
        g_boff[t] = s - v;
    }
    int L = g_deg_n[t] + 1;
    g_dinv_n[t] = rsqrtf((float)L);
    int s = L;
    for (int o = 1; o < 32; o <<= 1) {
        int u = __shfl_up_sync(0xffffffffu, s, o);
        if (lane >= o) s += u;
    }
    if (lane == 31) ws[w] = s;
    __syncthreads();
    int off = 0;
    for (int k = 0; k < 4; k++) off += (k < w) ? ws[k] : 0;
    int ex = s - L + off;
    g_rs_n[t] = ex;
    g_cur_n[t] = ex;
    if (t == 0) g_rs_n[NNV] = TOTN;
}

// ---------------- pass 3: add block offsets, init cursors -------------------
__global__ void k_scan3() {
    int i = blockIdx.x * blockDim.x + threadIdx.x;   // NPV threads
    int v = g_rs_p[i] + g_boff[i >> 10];
    g_rs_p[i] = v;
    g_cur_p[i] = v;
    if (i == 0) g_rs_p[NPV] = TOTP;
}

// ---------------- CSR fill (edges + self loops, with norms) ----------------
__global__ void k_fill(const void* __restrict__ eip, const void* __restrict__ ein) {
    int i = blockIdx.x * blockDim.x + threadIdx.x;
    if (i < EPV) {
        int is64 = !g_not64_p;
        int s = eget(eip, is64, i);
        int d = eget(eip, is64, EPV + i);
        float w = g_dinv_p[s] * g_dinv_p[d];
        int pos = atomicAdd(&g_cur_p[d], 1);
        g_colw_p[pos] = make_int2(s, __float_as_int(w));
    } else if (i < EPV + NPV) {
        int n = i - EPV;
        float di = g_dinv_p[n];
        int pos = atomicAdd(&g_cur_p[n], 1);
        g_colw_p[pos] = make_int2(n, __float_as_int(di * di));
    } else if (i < EPV + NPV + ENV) {
        int j = i - EPV - NPV;
        int is64 = !g_not64_n;
        int s = eget(ein, is64, j);
        int d = eget(ein, is64, ENV + j);
        float w = g_dinv_n[s] * g_dinv_n[d];
        int pos = atomicAdd(&g_cur_n[d], 1);
        g_colw_n[pos] = make_int2(s, __float_as_int(w));
    } else if (i < EPV + NPV + ENV + NNV) {
        int n = i - EPV - NPV - ENV;
        float di = g_dinv_n[n];
        int pos = atomicAdd(&g_cur_n[n], 1);
        g_colw_n[pos] = make_int2(n, __float_as_int(di * di));
    }
}

// ---------------- all W powers in ONE kernel: row-resident recurrence -------
// P_t[r,:] = P_{t-1}[r,:] @ W is independent per row r. Block r keeps its row
// in SMEM and iterates all WALKN powers; W is L1-resident after first sweep.
// Block CH handles the bias row b^T W^t and publishes the b!=0 flag.
__global__ void k_wpow_all(const float* __restrict__ W, const float* __restrict__ bg) {
    __shared__ float prev[CH];
    int c = threadIdx.x;
    int r = blockIdx.x;
    prev[c] = (r < CH) ? ((c == r) ? 1.0f : 0.0f) : bg[c];
    if (r == CH) {
        int nz = __syncthreads_or(prev[c] != 0.0f);
        if (c == 0) g_bnz = nz;
    }
    __syncthreads();
    for (int t = 1; t <= WALKN; t++) {
        float acc = 0.0f;
#pragma unroll 16
        for (int m = 0; m < CH; m++) acc = fmaf(prev[m], W[m * CH + c], acc);
        __syncthreads();
        prev[c] = acc;
        if (r < CH) g_PT[t * CC + c * CH + r] = acc;   // transposed for fused trace
        else        g_Bv[t * CH + c] = acc;
        __syncthreads();
    }
}

// ---------------- main per-step kernel: g <- A g, (c <- A c), fused traces --
__global__ void __launch_bounds__(256) k_agg(const float* __restrict__ xp,
                                             const float* __restrict__ xnp,
                                             int a, int last) {
    int gw   = blockIdx.x * 8 + (threadIdx.x >> 5);   // warp per dst row
    int lane = threadIdx.x & 31;
    int pa = (a - 1) & 1, ca = a & 1;
    int bnz = g_bnz;                                  // b==0 fast path (uniform)
    int cpath = bnz && !last;

    if (gw < NPV) {
        const float4* g4  = (const float4*)((a == 1) ? xp : g_g[pa]);
        const float*  cin = g_c[pa];
        int s0 = g_rs_p[gw], s1 = g_rs_p[gw + 1];
        float ax = 0.f, ay = 0.f, az = 0.f, aw = 0.f, cacc = 0.f;
        int e = s0;
        for (; e + 2 <= s1; e += 2) {                 // 2-deep pipeline (MLP)
            int2 cw0 = g_colw_p[e];
            int2 cw1 = g_colw_p[e + 1];
            float4 v0 = g4[cw0.x * 32 + lane];
            float4 v1 = g4[cw1.x * 32 + lane];
            float w0 = __int_as_float(cw0.y), w1 = __int_as_float(cw1.y);
            ax = fmaf(w0, v0.x, ax); ay = fmaf(w0, v0.y, ay);
            az = fmaf(w0, v0.z, az); aw = fmaf(w0, v0.w, aw);
            ax = fmaf(w1, v1.x, ax); ay = fmaf(w1, v1.y, ay);
            az = fmaf(w1, v1.z, az); aw = fmaf(w1, v1.w, aw);
            if (cpath && lane == 0) cacc += w0 * cin[cw0.x] + w1 * cin[cw1.x];
        }
        if (e < s1) {
            int2 cw0 = g_colw_p[e];
            float4 v0 = g4[cw0.x * 32 + lane];
            float w0 = __int_as_float(cw0.y);
            ax = fmaf(w0, v0.x, ax); ay = fmaf(w0, v0.y, ay);
            az = fmaf(w0, v0.z, az); aw = fmaf(w0, v0.w, aw);
            if (cpath && lane == 0) cacc += w0 * cin[cw0.x];
        }
        if (!last)   // g_WALKN never consumed downstream
            ((float4*)g_g[ca])[gw * 32 + lane] = make_float4(ax, ay, az, aw);

        // fused block trace: row r=gw contributes  g[r,:] . W^a[:, r&127]
        int k = gw & 127, bb = gw >> 7;
        float4 wt = ((const float4*)(g_PT + a * CC + k * CH))[lane];
        float part = ax * wt.x + ay * wt.y + az * wt.z + aw * wt.w;
        part += __shfl_xor_sync(0xffffffffu, part, 16);
        part += __shfl_xor_sync(0xffffffffu, part, 8);
        part += __shfl_xor_sync(0xffffffffu, part, 4);
        part += __shfl_xor_sync(0xffffffffu, part, 2);
        part += __shfl_xor_sync(0xffffffffu, part, 1);
        if (lane == 0) {
            atomicAdd(&g_ptr[(a - 1) * BATN + bb], part);
            if (cpath) {
                g_c[ca][gw] = cacc;
                atomicAdd(&g_q[(a - 1) * BATN + bb], cacc * g_Bv[a * CH + k]);
            }
        }
    } else {
        int w2 = gw - NPV;                            // np graph, 128 dst rows
        const float4* g4  = (const float4*)((a == 1) ? xnp : g_gn[pa]);
        const float*  cin = g_cn[pa];
        int s0 = g_rs_n[w2], s1 = g_rs_n[w2 + 1];
        float ax = 0.f, ay = 0.f, az = 0.f, aw = 0.f, cacc = 0.f;
        for (int e = s0; e < s1; e++) {
            int2 cw0 = g_colw_n[e];
            float4 v0 = g4[cw0.x * 32 + lane];
            float w0 = __int_as_float(cw0.y);
            ax = fmaf(w0, v0.x, ax); ay = fmaf(w0, v0.y, ay);
            az = fmaf(w0, v0.z, az); aw = fmaf(w0, v0.w, aw);
            if (cpath && lane == 0) cacc += w0 * cin[cw0.x];
        }
        if (!last)
            ((float4*)g_gn[ca])[w2 * 32 + lane] = make_float4(ax, ay, az, aw);
        float4 wt = ((const float4*)(g_PT + a * CC + w2 * CH))[lane];
        float part = ax * wt.x + ay * wt.y + az * wt.z + aw * wt.w;
        part += __shfl_xor_sync(0xffffffffu, part, 16);
        part += __shfl_xor_sync(0xffffffffu, part, 8);
        part += __shfl_xor_sync(0xffffffffu, part, 4);
        part += __shfl_xor_sync(0xffffffffu, part, 2);
        part += __shfl_xor_sync(0xffffffffu, part, 1);
        if (lane == 0) {
            atomicAdd(&g_ntr[a - 1], part);
            if (cpath) {
                g_cn[ca][w2] = cacc;
                atomicAdd(&g_qn[a - 1], cacc * g_Bv[a * CH + w2]);
            }
        }
    }
}

// ---------------- epilogue: bias corr, standardize, MLP, sigmoid ------------
__global__ void k_epi(const float* __restrict__ y,  const float* __restrict__ bg,
                      const float* __restrict__ W1, const float* __restrict__ b1,
                      const float* __restrict__ W2, const float* __restrict__ b2,
                      float* __restrict__ out) {
    __shared__ float sh[BATN];
    int b = threadIdx.x;
    float sumb = 0.f;
    for (int k = 0; k < CH; k++) sumb += bg[k];
    float ysc = (y[b] - 0.5f) * 2.0f;

    float v[WALKN];
    float cp = 0.f, cn = 0.f;
    for (int s = 0; s < WALKN; s++) {
        float qp = (s == 0) ? sumb : g_q[(s - 1) * BATN + b];
        float qn = (s == 0) ? sumb : g_qn[s - 1];
        cp += qp; cn += qn;
        float pv = g_ptr[s * BATN + b] + cp;
        float nv = g_ntr[s] + cn;
        v[s] = (pv - nv) * ysc;
    }
    for (int s = 0; s < WALKN; s++) {
        __syncthreads();
        sh[b] = v[s];
        __syncthreads();
        for (int ofs = 128; ofs > 0; ofs >>= 1) {
            if (b < ofs) sh[b] += sh[b + ofs];
            __syncthreads();
        }
        float mu = sh[0] * (1.0f / BATN);
        __syncthreads();
        float d = v[s] - mu;
        sh[b] = d * d;
        __syncthreads();
        for (int ofs = 128; ofs > 0; ofs >>= 1) {
            if (b < ofs) sh[b] += sh[b + ofs];
            __syncthreads();
        }
        float sd = sqrtf(sh[0] * (1.0f / (BATN - 1)));
        v[s] = d / sd;
    }
    float o2 = b2[0];
    for (int j = 0; j < 15; j++) {
        float h = b1[j];
        for (int s = 0; s < WALKN; s++) h = fmaf(v[s], W1[s * 15 + j], h);
        h = fmaxf(h, 0.0f);
        o2 = fmaf(h, W2[j], o2);
    }
    out[b] = 1.0f / (1.0f + expf(-o2));
    if (b == 0) { g_not64_p = 0; g_not64_n = 0; }   // restore load-time state
}

// ---------------- launch ----------------
extern "C" void kernel_launch(void* const* d_in, const int* in_sizes, int n_in,
                              void* d_out, int out_size) {
    const float* x_p  = (const float*)d_in[0];
    const float* x_np = (const float*)d_in[1];
    const float* y    = (const float*)d_in[2];
    const void*  eip  = d_in[3];
    const void*  ein  = d_in[4];
    const float* W    = (const float*)d_in[5];
    const float* bg   = (const float*)d_in[6];
    const float* W1   = (const float*)d_in[7];
    const float* b1   = (const float*)d_in[8];
    const float* W2   = (const float*)d_in[9];
    const float* b2   = (const float*)d_in[10];
    float* out = (float*)d_out;

    k_prep<<<(EPV + ENV) / 256, 256>>>(eip, ein);
    k_deg<<<(EPV + ENV) / 256, 256>>>(eip, ein);
    k_scan1<<<32, 1024>>>();
    k_scan2<<<1, 128>>>();
    k_scan3<<<NPV / 256, 256>>>();
    k_fill<<<(EPV + NPV + ENV + NNV + 255) / 256, 256>>>(eip, ein);
    k_wpow_all<<<CH + 1, CH>>>(W, bg);
    for (int a = 1; a <= WALKN; a++)
        k_agg<<<(NPV + NNV) / 8, 256>>>(x_p, x_np, a, a == WALKN);
    k_epi<<<1, BATN>>>(y, bg, W1, b1, W2, b2, out);
    (void)in_sizes; (void)n_in; (void)out_size;
}